// round 5
// baseline (speedup 1.0000x reference)
#include <cuda_runtime.h>
#include <cuda_bf16.h>
#include <cstdint>
#include <math.h>

#define NN 100000
#define EE 1000000
#define DD 128
#define KK 256

#define BM 64
#define THREADS 1024
#define NBLK ((NN + BM - 1) / BM)     // 1563

#define XS_PITCH 260                   // floats per row (256 + 4 pad)
#define WS_FLOATS (KK * DD)            // 32768
#define SMEM_FLOATS (WS_FLOATS + BM * XS_PITCH)

// Scratch
__device__ int  g_cnt[NN];
__device__ int  g_off[NN];
__device__ int  g_cur[NN];
__device__ int  g_total;
__device__ int2 g_meta[EE];            // {src, w_as_int}

// ---------------------------------------------------------------------------
// CSR build
// ---------------------------------------------------------------------------
__global__ void hist_kernel(const int* __restrict__ dst, int* __restrict__ cnt)
{
    int e = blockIdx.x * blockDim.x + threadIdx.x;
    if (e < EE) atomicAdd(&cnt[__ldg(dst + e)], 1);
}

__global__ void alloc_kernel(const int* __restrict__ cnt,
                             int* __restrict__ off,
                             int* __restrict__ cur,
                             int* __restrict__ total)
{
    int i = blockIdx.x * blockDim.x + threadIdx.x;
    if (i < NN) {
        int o = atomicAdd(total, cnt[i]);
        off[i] = o;
        cur[i] = o;
    }
}

__global__ void scatter_kernel(const int* __restrict__ src,
                               const int* __restrict__ dst,
                               const float* __restrict__ norm,
                               int* __restrict__ cur,
                               int2* __restrict__ meta)
{
    int e = blockIdx.x * blockDim.x + threadIdx.x;
    if (e >= EE) return;
    int s = __ldg(src + e);
    int d = __ldg(dst + e);
    float w = __ldg(norm + s) * __ldg(norm + d);
    int pos = atomicAdd(&cur[d], 1);
    meta[pos] = make_int2(s, __float_as_int(w));
}

// ---------------------------------------------------------------------------
// Fused: aggregate 64 nodes into SMEM, GEMM vs W=[W1;W2], leaky+L2norm, store.
// 1024 threads = 32 warps. Aggregate: warp w -> nodes [base+2w, base+2w+2).
// GEMM: tx = tid&31 (4 cols), ty = tid>>5 (2 rows); acc in packed f32x2.
// ---------------------------------------------------------------------------
__device__ __forceinline__ void cp_async16(unsigned int dst, const void* src)
{
    asm volatile("cp.async.cg.shared.global [%0], [%1], 16;"
                 :: "r"(dst), "l"(src) : "memory");
}

__global__ void __launch_bounds__(THREADS, 1)
fused_kernel(const float4* __restrict__ ego,
             const int*   __restrict__ off,
             const int*   __restrict__ cnt,
             const int2*  __restrict__ meta,
             const float* __restrict__ W1,
             const float* __restrict__ W2,
             float*       __restrict__ out)
{
    extern __shared__ float smem[];
    float* Ws = smem;                   // [256][128]
    float* Xs = smem + WS_FLOATS;       // [64][260]

    const int tid  = threadIdx.x;
    const int lane = tid & 31;
    const int warp = tid >> 5;
    const int rowBase = blockIdx.x * BM;

    // ---- 1) issue async copy of W = [W1;W2] into SMEM (overlaps aggregate)
    {
        unsigned int wsBase;
        asm("{ .reg .u64 t; cvta.to.shared.u64 t, %1; cvt.u32.u64 %0, t; }"
            : "=r"(wsBase) : "l"(Ws));
        const float4* W1v = (const float4*)W1;
        const float4* W2v = (const float4*)W2;
        #pragma unroll
        for (int i = 0; i < 8; ++i) {
            int m  = tid + i * THREADS;     // 0..8191 (float4 idx)
            int k  = m >> 5;
            int j4 = m & 31;
            const void* src = (k < DD) ? (const void*)&W1v[(size_t)k * 32 + j4]
                                       : (const void*)&W2v[(size_t)(k - DD) * 32 + j4];
            cp_async16(wsBase + m * 16, src);
        }
        asm volatile("cp.async.commit_group;" ::: "memory");
    }

    // ---- 2) aggregate 2 nodes per warp into Xs
    #pragma unroll
    for (int q = 0; q < 2; ++q) {
        int node = rowBase + warp * 2 + q;
        bool valid = node < NN;

        float4 hd = valid ? __ldg(ego + (size_t)node * 32 + lane)
                          : make_float4(0.f, 0.f, 0.f, 0.f);
        float4 a = hd;                      // self term
        float4 b = make_float4(0.f, 0.f, 0.f, 0.f);

        int n  = valid ? __ldg(cnt + node) : 0;
        int e0 = valid ? __ldg(off + node) : 0;

        for (int c = 0; c < n; c += 32) {
            int lim = min(32, n - c);
            int2 mm = (lane < lim) ? __ldg(meta + e0 + c + lane)
                                   : make_int2(0, 0);
            int j = 0;
            for (; j + 4 <= lim; j += 4) {
                int   s0 = __shfl_sync(0xffffffffu, mm.x, j + 0);
                int   s1 = __shfl_sync(0xffffffffu, mm.x, j + 1);
                int   s2 = __shfl_sync(0xffffffffu, mm.x, j + 2);
                int   s3 = __shfl_sync(0xffffffffu, mm.x, j + 3);
                float w0 = __int_as_float(__shfl_sync(0xffffffffu, mm.y, j + 0));
                float w1 = __int_as_float(__shfl_sync(0xffffffffu, mm.y, j + 1));
                float w2 = __int_as_float(__shfl_sync(0xffffffffu, mm.y, j + 2));
                float w3 = __int_as_float(__shfl_sync(0xffffffffu, mm.y, j + 3));
                float4 h0 = __ldg(ego + (size_t)s0 * 32 + lane);
                float4 h1 = __ldg(ego + (size_t)s1 * 32 + lane);
                float4 h2 = __ldg(ego + (size_t)s2 * 32 + lane);
                float4 h3 = __ldg(ego + (size_t)s3 * 32 + lane);
                float t;
                t = w0 * h0.x; a.x += t; b.x = fmaf(t, hd.x, b.x);
                t = w0 * h0.y; a.y += t; b.y = fmaf(t, hd.y, b.y);
                t = w0 * h0.z; a.z += t; b.z = fmaf(t, hd.z, b.z);
                t = w0 * h0.w; a.w += t; b.w = fmaf(t, hd.w, b.w);
                t = w1 * h1.x; a.x += t; b.x = fmaf(t, hd.x, b.x);
                t = w1 * h1.y; a.y += t; b.y = fmaf(t, hd.y, b.y);
                t = w1 * h1.z; a.z += t; b.z = fmaf(t, hd.z, b.z);
                t = w1 * h1.w; a.w += t; b.w = fmaf(t, hd.w, b.w);
                t = w2 * h2.x; a.x += t; b.x = fmaf(t, hd.x, b.x);
                t = w2 * h2.y; a.y += t; b.y = fmaf(t, hd.y, b.y);
                t = w2 * h2.z; a.z += t; b.z = fmaf(t, hd.z, b.z);
                t = w2 * h2.w; a.w += t; b.w = fmaf(t, hd.w, b.w);
                t = w3 * h3.x; a.x += t; b.x = fmaf(t, hd.x, b.x);
                t = w3 * h3.y; a.y += t; b.y = fmaf(t, hd.y, b.y);
                t = w3 * h3.z; a.z += t; b.z = fmaf(t, hd.z, b.z);
                t = w3 * h3.w; a.w += t; b.w = fmaf(t, hd.w, b.w);
            }
            for (; j < lim; ++j) {
                int   s0 = __shfl_sync(0xffffffffu, mm.x, j);
                float w0 = __int_as_float(__shfl_sync(0xffffffffu, mm.y, j));
                float4 h0 = __ldg(ego + (size_t)s0 * 32 + lane);
                float t;
                t = w0 * h0.x; a.x += t; b.x = fmaf(t, hd.x, b.x);
                t = w0 * h0.y; a.y += t; b.y = fmaf(t, hd.y, b.y);
                t = w0 * h0.z; a.z += t; b.z = fmaf(t, hd.z, b.z);
                t = w0 * h0.w; a.w += t; b.w = fmaf(t, hd.w, b.w);
            }
        }

        int r = warp * 2 + q;
        *(float4*)&Xs[(size_t)r * XS_PITCH + lane * 4]       = a;
        *(float4*)&Xs[(size_t)r * XS_PITCH + DD + lane * 4]  = b;
    }

    asm volatile("cp.async.wait_group 0;" ::: "memory");
    __syncthreads();

    // ---- 3) GEMM: 64x128 tile, thread tile 2 rows x 4 cols (2 f32x2 pairs)
    const int tx  = tid & 31;        // col group: cols tx*4 .. tx*4+3
    const int ty  = tid >> 5;        // row group: rows ty*2 .. ty*2+1
    const int ty2 = ty * 2;
    const int tx4 = tx * 4;

    unsigned long long acc2[2][2];
    acc2[0][0] = 0ull; acc2[0][1] = 0ull;
    acc2[1][0] = 0ull; acc2[1][1] = 0ull;

    #pragma unroll 4
    for (int kb = 0; kb < KK; kb += 4) {
        float4 xr[2];
        xr[0] = *(const float4*)&Xs[(size_t)(ty2 + 0) * XS_PITCH + kb];
        xr[1] = *(const float4*)&Xs[(size_t)(ty2 + 1) * XS_PITCH + kb];

        #pragma unroll
        for (int kk = 0; kk < 4; ++kk) {
            const unsigned long long* wq =
                (const unsigned long long*)&Ws[(size_t)(kb + kk) * DD + tx4];
            unsigned long long w0 = wq[0], w1 = wq[1];
            #pragma unroll
            for (int i = 0; i < 2; ++i) {
                float x = (kk == 0) ? xr[i].x : (kk == 1) ? xr[i].y
                        : (kk == 2) ? xr[i].z : xr[i].w;
                unsigned long long xd;
                asm("mov.b64 %0, {%1, %1};" : "=l"(xd) : "f"(x));
                asm("fma.rn.f32x2 %0, %1, %2, %0;" : "+l"(acc2[i][0]) : "l"(xd), "l"(w0));
                asm("fma.rn.f32x2 %0, %1, %2, %0;" : "+l"(acc2[i][1]) : "l"(xd), "l"(w1));
            }
        }
    }

    // ---- 4) epilogue: leaky relu, row L2 norm via warp butterfly, store
    float acc[2][4];
    float p[2];
    #pragma unroll
    for (int i = 0; i < 2; ++i) {
        unsigned int lo, hi;
        asm("mov.b64 {%0, %1}, %2;" : "=r"(lo), "=r"(hi) : "l"(acc2[i][0]));
        acc[i][0] = __uint_as_float(lo);
        acc[i][1] = __uint_as_float(hi);
        asm("mov.b64 {%0, %1}, %2;" : "=r"(lo), "=r"(hi) : "l"(acc2[i][1]));
        acc[i][2] = __uint_as_float(lo);
        acc[i][3] = __uint_as_float(hi);
        float s = 0.f;
        #pragma unroll
        for (int j = 0; j < 4; ++j) {
            float v = acc[i][j];
            v = (v >= 0.f) ? v : 0.2f * v;
            acc[i][j] = v;
            s = fmaf(v, v, s);
        }
        p[i] = s;
    }
    #pragma unroll
    for (int o = 16; o > 0; o >>= 1) {
        p[0] += __shfl_xor_sync(0xffffffffu, p[0], o);
        p[1] += __shfl_xor_sync(0xffffffffu, p[1], o);
    }

    float4* out4 = (float4*)out;
    #pragma unroll
    for (int i = 0; i < 2; ++i) {
        int grow = rowBase + ty2 + i;
        if (grow < NN) {
            float inv = 1.0f / fmaxf(sqrtf(p[i]), 1e-12f);
            out4[(size_t)grow * 32 + tx] =
                make_float4(acc[i][0] * inv, acc[i][1] * inv,
                            acc[i][2] * inv, acc[i][3] * inv);
        }
    }
}

// ---------------------------------------------------------------------------
// Launch
// ---------------------------------------------------------------------------
extern "C" void kernel_launch(void* const* d_in, const int* in_sizes, int n_in,
                              void* d_out, int out_size)
{
    const float* ego  = (const float*)d_in[0];
    const float* norm = (const float*)d_in[1];
    const int*   src  = (const int*)d_in[2];
    const int*   dst  = (const int*)d_in[3];
    const float* W1   = (const float*)d_in[4];
    const float* W2   = (const float*)d_in[5];
    float* out = (float*)d_out;

    int*  cnt;   cudaGetSymbolAddress((void**)&cnt,   g_cnt);
    int*  off;   cudaGetSymbolAddress((void**)&off,   g_off);
    int*  cur;   cudaGetSymbolAddress((void**)&cur,   g_cur);
    int*  total; cudaGetSymbolAddress((void**)&total, g_total);
    int2* meta;  cudaGetSymbolAddress((void**)&meta,  g_meta);

    cudaMemsetAsync(cnt, 0, NN * sizeof(int));
    cudaMemsetAsync(total, 0, sizeof(int));
    hist_kernel<<<(EE + 255) / 256, 256>>>(dst, cnt);
    alloc_kernel<<<(NN + 255) / 256, 256>>>(cnt, off, cur, total);
    scatter_kernel<<<(EE + 255) / 256, 256>>>(src, dst, norm, cur, meta);

    int smem = SMEM_FLOATS * (int)sizeof(float);   // ~193 KB
    cudaFuncSetAttribute(fused_kernel,
                         cudaFuncAttributeMaxDynamicSharedMemorySize, smem);
    fused_kernel<<<NBLK, THREADS, smem>>>(
        (const float4*)ego, off, cnt, meta, W1, W2, out);
}